// round 13
// baseline (speedup 1.0000x reference)
#include <cuda_runtime.h>
#include <cuda_fp16.h>

#define GRID    128
#define NTH     1024
#define N_ATOMS 512
#define FDIM    128
#define NKER    301
#define NLAYER  3
#define NG2     704            // fine grid rows, t_g = g*0.025
#define INV_H2  40.0f
#define LN2     0.69314718056f

// ---- persistent device scratch (no runtime allocation) ----
__device__ __half g_WTABh[NLAYER * NG2 * FDIM];
__device__ float  g_O[2][N_ATOMS * FDIM];      // double-buffered atomwise output
__device__ unsigned g_bar_cnt;
__device__ unsigned g_bar_gen;

// ---- shared memory layout (bytes) ----
#define SM_WT     0                            // fp16 table: 704*128*2 = 180224
#define SM_RED    0                            // [32][4][128] f32 partials (aliases table)
#define SM_CWOFF  180224                       // uint2[4][512] {off, x half2} -> +16384
#define SM_HSM    (SM_CWOFF + 16384)           // float[4][128] h    -> +2048
#define SM_CPS    (SM_HSM + 2048)              // float[4][128] cpre -> +2048
#define SM_RI     (SM_CPS + 2048)              // float[4][4]        -> +64
#define SM_TOTAL  (SM_RI + 64)                 // = 200768

__device__ __forceinline__ float sspf(float v) {
    float e = __expf(-fabsf(v));
    return fmaxf(v, 0.0f) + __logf(1.0f + e) - LN2;
}

// grid barrier: count + monotonically increasing generation
__device__ __forceinline__ void gbar(unsigned target) {
    __syncthreads();
    if (threadIdx.x == 0) {
        __threadfence();
        unsigned prev = atomicAdd(&g_bar_cnt, 1u);
        if (prev == GRID - 1) {
            g_bar_cnt = 0u;
            __threadfence();
            atomicAdd(&g_bar_gen, 1u);
        } else {
            while (*(volatile unsigned*)&g_bar_gen != target) __nanosleep(64);
        }
    }
    __syncthreads();
    __threadfence();   // invalidate L1 before cross-CTA reads
}

// o[i0+a, f] = b[f] + sum_k hsm[a,k] * W[k,f]   (tid < 512 active)
__device__ __forceinline__ void atomwise_phase(const float* __restrict__ W,
                                               const float* __restrict__ b,
                                               const float* hsm, float* obuf,
                                               int i0, int tid) {
    if (tid < 512) {
        int f = tid & 127, a = tid >> 7;
        float acc = b[f];
#pragma unroll 8
        for (int k = 0; k < FDIM; k++)
            acc = fmaf(hsm[a * FDIM + k], W[k * FDIM + f], acc);
        obuf[(i0 + a) * FDIM + f] = acc;
    }
}

// h += ssp(cps @ W1 + b1) @ W2 + b2   (tid < 512 active; all threads hit syncthreads)
__device__ __forceinline__ void norm_phase(const float* __restrict__ W1,
                                           const float* __restrict__ b1,
                                           const float* __restrict__ W2,
                                           const float* __restrict__ b2,
                                           const float* cps, float* hsm,
                                           float* tsm, int tid) {
    int f = tid & 127, a = (tid >> 7) & 3;
    if (tid < 512) {
        float acc = b1[f];
#pragma unroll 8
        for (int k = 0; k < FDIM; k++)
            acc = fmaf(cps[a * FDIM + k], W1[k * FDIM + f], acc);
        tsm[a * FDIM + f] = sspf(acc);
    }
    __syncthreads();
    if (tid < 512) {
        float acc2 = b2[f];
#pragma unroll 8
        for (int k = 0; k < FDIM; k++)
            acc2 = fmaf(tsm[a * FDIM + k], W2[k * FDIM + f], acc2);
        hsm[a * FDIM + f] += acc2;
    }
}

// ---------------------------------------------------------------------------
__global__ void __launch_bounds__(NTH, 1)
schnet_fused(const int* __restrict__ x, const float* __restrict__ r,
             const float* __restrict__ emb,
             const float* __restrict__ aw_W, const float* __restrict__ aw_b,
             const float* __restrict__ cf_W1, const float* __restrict__ cf_b1,
             const float* __restrict__ cf_W2, const float* __restrict__ cf_b2,
             const float* __restrict__ n_W1, const float* __restrict__ n_b1,
             const float* __restrict__ n_W2, const float* __restrict__ n_b2,
             const float* __restrict__ out_W1, const float* __restrict__ out_b1,
             const float* __restrict__ out_W2, const float* __restrict__ out_b2,
             float* __restrict__ out)
{
    extern __shared__ char sm[];
    float* hsm = (float*)(sm + SM_HSM);
    float* cps = (float*)(sm + SM_CPS);
    float* ri  = (float*)(sm + SM_RI);
    const int tid = threadIdx.x;
    const int i0  = blockIdx.x * 4;

    unsigned gen0 = (tid == 0) ? *(volatile unsigned*)&g_bar_gen : 0u;
    unsigned nbar = 0;

    // ================= Phase A: embed, coords, interp params, aw0, tables =============
    if (tid < 512) {
        int f = tid & 127, a = tid >> 7;
        hsm[a * FDIM + f] = emb[x[i0 + a] * FDIM + f];
    }
    if (tid < 12) ri[(tid / 3) * 4 + (tid % 3)] = r[(i0 + tid / 3) * 3 + tid % 3];
    __syncthreads();

    // linear-interp params: byte offset of row gi + x packed as half2 (layer-independent)
    {
        uint2* cwp = (uint2*)(sm + SM_CWOFF);
#pragma unroll
        for (int it = 0; it < 2; it++) {
            int idx = tid + it * NTH;
            int a = idx >> 9, j = idx & 511;
            float dx = ri[a * 4 + 0] - r[j * 3 + 0];
            float dy = ri[a * 4 + 1] - r[j * 3 + 1];
            float dz = ri[a * 4 + 2] - r[j * 3 + 2];
            float d  = sqrtf(dx * dx + dy * dy + dz * dz);
            float aa = fminf(d * INV_H2, 702.0f);
            int   gi = (int)aa;
            float xx = aa - (float)gi;
            __half2 xh = __float2half2_rn(xx);
            uint2 v;
            v.x = (unsigned)(gi * (FDIM * 2));
            v.y = *(unsigned*)&xh;
            cwp[idx] = v;
        }
    }
    __syncthreads();
    atomwise_phase(aw_W, aw_b, hsm, g_O[0], i0, tid);

    // truncated-RBF table + filter MLP -> fp16 WTAB on fine grid.
    // 24-row chunks: 30 chunks/layer * 3 layers = 90 units, single pass over 128 CTAs.
    {
        float* esm = (float*)(sm + SM_WT);        // [24][40]
        float* ssm = esm + 24 * 40;               // [24][128]
        int u = blockIdx.x;
        if (u < 90) {
            int l = u / 30, g0 = (u % 30) * 24;
            float t0 = g0 * 0.025f;
            int kmin = (int)ceilf((t0 - 1.6f) * 10.0f);            if (kmin < 0) kmin = 0;
            int kmax = (int)floorf((t0 + 0.575f + 1.6f) * 10.0f);  if (kmax > NKER - 1) kmax = NKER - 1;
            int nk = kmax - kmin + 1;                              // <= 39
            if (tid < 24 * 40) {
                int rr = tid / 40, kk = tid % 40;
                float e = 0.0f;
                if (kk < nk) {
                    float uu = (g0 + rr) * 0.025f - 0.1f * (float)(kmin + kk);
                    e = __expf(-10.0f * uu * uu);
                }
                esm[rr * 40 + kk] = e;
            }
            __syncthreads();
            {
                int f = tid & 127, rh = tid >> 7;          // 3 rows each (rh 0..7)
                const float* W1 = cf_W1 + l * NKER * FDIM;
                float b1f = cf_b1[l * FDIM + f];
#pragma unroll
                for (int q = 0; q < 3; q++) {
                    int rr = rh * 3 + q;
                    float acc = 0.0f;
                    for (int kk = 0; kk < nk; kk++)
                        acc = fmaf(esm[rr * 40 + kk], W1[(kmin + kk) * FDIM + f], acc);
                    ssm[rr * FDIM + f] = sspf(acc + b1f);
                }
            }
            __syncthreads();
            {
                int f = tid & 127, rh = tid >> 7;          // 3 rows each
                const float* W2 = cf_W2 + l * FDIM * FDIM;
                float b2f = cf_b2[l * FDIM + f];
                float a0 = b2f, a1 = b2f, a2 = b2f;
#pragma unroll 4
                for (int k = 0; k < FDIM; k++) {
                    float w = W2[k * FDIM + f];
                    a0 = fmaf(ssm[(rh * 3 + 0) * FDIM + k], w, a0);
                    a1 = fmaf(ssm[(rh * 3 + 1) * FDIM + k], w, a1);
                    a2 = fmaf(ssm[(rh * 3 + 2) * FDIM + k], w, a2);
                }
                int g = g0 + rh * 3;
                if (g < NG2)     g_WTABh[(l * NG2 + g) * FDIM + f]     = __float2half_rn(sspf(a0));
                if (g + 1 < NG2) g_WTABh[(l * NG2 + g + 1) * FDIM + f] = __float2half_rn(sspf(a1));
                if (g + 2 < NG2) g_WTABh[(l * NG2 + g + 2) * FDIM + f] = __float2half_rn(sspf(a2));
            }
        }
    }
    gbar(gen0 + (++nbar));   // o buf0 + WTAB published

    // ==================== layer loop ====================
    for (int l = 0; l < NLAYER; l++) {
        const float* oBuf = g_O[l & 1];
        // ---- conv: cps[a,f] = sum_j o[j,f] * lin_interp(WTAB_l, d_aj)[f] ----
        {
            // stage fp16 table slice (11 x uint4 per thread)
            uint4* dst = (uint4*)(sm + SM_WT);
            const uint4* src = (const uint4*)(g_WTABh + l * NG2 * FDIM);
#pragma unroll
            for (int it = 0; it < (NG2 * FDIM * 2 / 16) / NTH; it++)
                dst[tid + it * NTH] = src[tid + it * NTH];
            __syncthreads();

            const int fp = tid & 31;      // 4 features: fp*4 .. fp*4+3
            const int jg = tid >> 5;      // warp id 0..31, one j per warp
            const char*  WTb = sm + SM_WT;
            const uint2* cwp = (const uint2*)(sm + SM_CWOFF);
            const __half2 ONE2 = __float2half2_rn(1.0f);

            float acc[4][4];
#pragma unroll
            for (int a = 0; a < 4; a++)
#pragma unroll
                for (int c = 0; c < 4; c++) acc[a][c] = 0.0f;

            const float* oPtr = oBuf + fp * 4;
            float4 ov = *(const float4*)(oPtr + jg * FDIM);
            for (int j = jg; j < N_ATOMS; j += 32) {
                // prefetch next o row (register double-buffer, hides L2 latency)
                float4 ovn = ov;
                int jn = j + 32;
                if (jn < N_ATOMS) ovn = *(const float4*)(oPtr + jn * FDIM);
#pragma unroll
                for (int a = 0; a < 4; a++) {
                    uint2 co = cwp[a * N_ATOMS + j];    // broadcast
                    __half2 xh  = *(__half2*)&co.y;
                    __half2 oxh = __hsub2(ONE2, xh);
                    const char* T = WTb + co.x + fp * 8;
                    uint2 q0 = *(const uint2*)(T);
                    uint2 q1 = *(const uint2*)(T + 256);
                    __half2 w0 = __hfma2(xh, *(__half2*)&q1.x,
                                 __hmul2(oxh, *(__half2*)&q0.x));
                    __half2 w1 = __hfma2(xh, *(__half2*)&q1.y,
                                 __hmul2(oxh, *(__half2*)&q0.y));
                    float2 wf0 = __half22float2(w0);
                    float2 wf1 = __half22float2(w1);
                    acc[a][0] = fmaf(ov.x, wf0.x, acc[a][0]);
                    acc[a][1] = fmaf(ov.y, wf0.y, acc[a][1]);
                    acc[a][2] = fmaf(ov.z, wf1.x, acc[a][2]);
                    acc[a][3] = fmaf(ov.w, wf1.y, acc[a][3]);
                }
                ov = ovn;
            }

            // one partial per warp -> smem (aliases table region), tree-reduce
            __syncthreads();                      // all table reads done before overwrite
            float* red = (float*)(sm + SM_RED);   // [32][4][128]
#pragma unroll
            for (int a = 0; a < 4; a++)
                *(float4*)(red + (jg * 4 + a) * FDIM + fp * 4) =
                    make_float4(acc[a][0], acc[a][1], acc[a][2], acc[a][3]);
            __syncthreads();
            if (tid < 512) {
                int a = tid >> 7, f = tid & 127;
                float s = 0.0f;
#pragma unroll
                for (int g = 0; g < 32; g++) s += red[(g * 4 + a) * FDIM + f];
                cps[a * FDIM + f] = s;
            }
            __syncthreads();
        }

        if (l < NLAYER - 1) {
            norm_phase(n_W1 + l * FDIM * FDIM, n_b1 + l * FDIM,
                       n_W2 + l * FDIM * FDIM, n_b2 + l * FDIM,
                       cps, hsm, (float*)(sm + SM_RED), tid);
            __syncthreads();
            atomwise_phase(aw_W + (l + 1) * FDIM * FDIM, aw_b + (l + 1) * FDIM,
                           hsm, g_O[(l + 1) & 1], i0, tid);
            gbar(gen0 + (++nbar));   // new o published
        }
    }

    // ---- final norm + output head (CTA-local) ----
    norm_phase(n_W1 + 2 * FDIM * FDIM, n_b1 + 2 * FDIM,
               n_W2 + 2 * FDIM * FDIM, n_b2 + 2 * FDIM,
               cps, hsm, (float*)(sm + SM_RED), tid);
    __syncthreads();
    if (tid < 128) {
        int wid = tid >> 5, lane = tid & 31;
        const float* hrow = hsm + wid * FDIM;
        float acc = out_b1[lane];
#pragma unroll 8
        for (int k = 0; k < FDIM; k++)
            acc = fmaf(hrow[k], out_W1[k * 32 + lane], acc);
        float u = sspf(acc) * out_W2[lane];
#pragma unroll
        for (int off = 16; off > 0; off >>= 1)
            u += __shfl_down_sync(0xffffffffu, u, off);
        if (lane == 0) out[i0 + wid] = u + out_b2[0];
    }
}

// ---------------------------------------------------------------------------
extern "C" void kernel_launch(void* const* d_in, const int* in_sizes, int n_in,
                              void* d_out, int out_size) {
    const int*   x      = (const int*)d_in[0];
    const float* r      = (const float*)d_in[1];
    const float* emb    = (const float*)d_in[2];
    const float* aw_W   = (const float*)d_in[3];
    const float* aw_b   = (const float*)d_in[4];
    const float* cf_W1  = (const float*)d_in[5];
    const float* cf_b1  = (const float*)d_in[6];
    const float* cf_W2  = (const float*)d_in[7];
    const float* cf_b2  = (const float*)d_in[8];
    const float* n_W1   = (const float*)d_in[9];
    const float* n_b1   = (const float*)d_in[10];
    const float* n_W2   = (const float*)d_in[11];
    const float* n_b2   = (const float*)d_in[12];
    const float* out_W1 = (const float*)d_in[13];
    const float* out_b1 = (const float*)d_in[14];
    const float* out_W2 = (const float*)d_in[15];
    const float* out_b2 = (const float*)d_in[16];
    float* out = (float*)d_out;

    cudaFuncSetAttribute(schnet_fused, cudaFuncAttributeMaxDynamicSharedMemorySize,
                         SM_TOTAL);
    schnet_fused<<<GRID, NTH, SM_TOTAL>>>(
        x, r, emb, aw_W, aw_b, cf_W1, cf_b1, cf_W2, cf_b2,
        n_W1, n_b1, n_W2, n_b2, out_W1, out_b1, out_W2, out_b2, out);
}

// round 17
// speedup vs baseline: 1.1540x; 1.1540x over previous
#include <cuda_runtime.h>
#include <cuda_fp16.h>

#define GRID    128
#define NTH     1024
#define N_ATOMS 512
#define FDIM    128
#define NKER    301
#define NLAYER  3
#define NG2     704            // fine grid rows, t_g = g*0.025
#define INV_H2  40.0f
#define LN2     0.69314718056f

// ---- persistent device scratch (no runtime allocation) ----
__device__ __half g_WTABh[NLAYER * NG2 * FDIM];
__device__ float  g_O[2][N_ATOMS * FDIM];      // double-buffered atomwise output
__device__ unsigned g_bar_cnt;
__device__ unsigned g_bar_gen;

// ---- shared memory layout (bytes) ----
#define SM_WT     0                            // fp16 table: 704*128*2 = 180224
#define SM_RED    0                            // [32][4][128] f32 partials (aliases table)
#define SM_CWOFF  180224                       // uint2[512][4] {off, x half2} -> +16384
#define SM_P2     196608                       // float[2][512] split-k partials -> +4096
#define SM_HSM    200704                       // float[4][128] h    -> +2048
#define SM_CPS    202752                       // float[4][128] cpre -> +2048
#define SM_RI     204800                       // float[4][4]        -> +64
#define SM_TOTAL  204864

__device__ __forceinline__ float sspf(float v) {
    float e = __expf(-fabsf(v));
    return fmaxf(v, 0.0f) + __logf(1.0f + e) - LN2;
}

// grid barrier: count + monotonically increasing generation
__device__ __forceinline__ void gbar(unsigned target) {
    __syncthreads();
    if (threadIdx.x == 0) {
        __threadfence();
        unsigned prev = atomicAdd(&g_bar_cnt, 1u);
        if (prev == GRID - 1) {
            g_bar_cnt = 0u;
            __threadfence();
            atomicAdd(&g_bar_gen, 1u);
        } else {
            while (*(volatile unsigned*)&g_bar_gen != target) __nanosleep(64);
        }
    }
    __syncthreads();
    __threadfence();   // invalidate L1 before cross-CTA reads
}

// o[i0+a, f] = b[f] + sum_k hsm[a,k] * W[k,f]   — split-k over 1024 threads
__device__ __forceinline__ void atomwise_phase(const float* __restrict__ W,
                                               const float* __restrict__ b,
                                               const float* hsm, float* obuf,
                                               float* p2, int i0, int tid) {
    int f = tid & 127, a = (tid >> 7) & 3, h = tid >> 9;
    const float* hp = hsm + a * FDIM + h * 64;
    const float* Wp = W + h * 64 * FDIM + f;
    float acc = 0.0f;
#pragma unroll 8
    for (int k = 0; k < 64; k++)
        acc = fmaf(hp[k], Wp[k * FDIM], acc);
    p2[h * 512 + (tid & 511)] = acc;
    __syncthreads();
    if (tid < 512)
        obuf[(i0 + a) * FDIM + f] = b[f] + p2[tid] + p2[512 + tid];
    __syncthreads();
}

// h += ssp(cps @ W1 + b1) @ W2 + b2   — split-k over 1024 threads
__device__ __forceinline__ void norm_phase(const float* __restrict__ W1,
                                           const float* __restrict__ b1,
                                           const float* __restrict__ W2,
                                           const float* __restrict__ b2,
                                           const float* cps, float* hsm,
                                           float* tsm, float* p2, int tid) {
    int f = tid & 127, a = (tid >> 7) & 3, h = tid >> 9;
    {
        const float* cp = cps + a * FDIM + h * 64;
        const float* Wp = W1 + h * 64 * FDIM + f;
        float acc = 0.0f;
#pragma unroll 8
        for (int k = 0; k < 64; k++)
            acc = fmaf(cp[k], Wp[k * FDIM], acc);
        p2[h * 512 + (tid & 511)] = acc;
    }
    __syncthreads();
    if (tid < 512)
        tsm[tid] = sspf(b1[f] + p2[tid] + p2[512 + tid]);
    __syncthreads();
    {
        const float* tp = tsm + a * FDIM + h * 64;
        const float* Wp = W2 + h * 64 * FDIM + f;
        float acc = 0.0f;
#pragma unroll 8
        for (int k = 0; k < 64; k++)
            acc = fmaf(tp[k], Wp[k * FDIM], acc);
        p2[h * 512 + (tid & 511)] = acc;
    }
    __syncthreads();
    if (tid < 512)
        hsm[tid] += b2[f] + p2[tid] + p2[512 + tid];
    __syncthreads();
}

// ---------------------------------------------------------------------------
__global__ void __launch_bounds__(NTH, 1)
schnet_fused(const int* __restrict__ x, const float* __restrict__ r,
             const float* __restrict__ emb,
             const float* __restrict__ aw_W, const float* __restrict__ aw_b,
             const float* __restrict__ cf_W1, const float* __restrict__ cf_b1,
             const float* __restrict__ cf_W2, const float* __restrict__ cf_b2,
             const float* __restrict__ n_W1, const float* __restrict__ n_b1,
             const float* __restrict__ n_W2, const float* __restrict__ n_b2,
             const float* __restrict__ out_W1, const float* __restrict__ out_b1,
             const float* __restrict__ out_W2, const float* __restrict__ out_b2,
             float* __restrict__ out)
{
    extern __shared__ char sm[];
    float* hsm = (float*)(sm + SM_HSM);
    float* cps = (float*)(sm + SM_CPS);
    float* ri  = (float*)(sm + SM_RI);
    float* p2  = (float*)(sm + SM_P2);
    const int tid = threadIdx.x;
    const int i0  = blockIdx.x * 4;

    unsigned gen0 = (tid == 0) ? *(volatile unsigned*)&g_bar_gen : 0u;
    unsigned nbar = 0;

    // ================= Phase A: embed, coords, interp params, aw0, tables =============
    if (tid < 512) {
        int f = tid & 127, a = tid >> 7;
        hsm[a * FDIM + f] = emb[x[i0 + a] * FDIM + f];
    }
    if (tid < 12) ri[(tid / 3) * 4 + (tid % 3)] = r[(i0 + tid / 3) * 3 + tid % 3];
    __syncthreads();

    // linear-interp params, layout [j][a]: byte offset of row gi + x packed half2
    {
        uint2* cwp = (uint2*)(sm + SM_CWOFF);
#pragma unroll
        for (int it = 0; it < 2; it++) {
            int idx = tid + it * NTH;      // idx = j*4 + a
            int j = idx >> 2, a = idx & 3;
            float dx = ri[a * 4 + 0] - r[j * 3 + 0];
            float dy = ri[a * 4 + 1] - r[j * 3 + 1];
            float dz = ri[a * 4 + 2] - r[j * 3 + 2];
            float d  = sqrtf(dx * dx + dy * dy + dz * dz);
            float aa = fminf(d * INV_H2, 702.0f);
            int   gi = (int)aa;
            float xx = aa - (float)gi;
            __half2 xh = __float2half2_rn(xx);
            uint2 v;
            v.x = (unsigned)(gi * (FDIM * 2));
            v.y = *(unsigned*)&xh;
            cwp[idx] = v;
        }
    }
    __syncthreads();
    atomwise_phase(aw_W, aw_b, hsm, g_O[0], p2, i0, tid);

    // truncated-RBF table + filter MLP -> fp16 WTAB on fine grid.
    // 24-row chunks: 30 chunks/layer * 3 layers = 90 units, single pass over 128 CTAs.
    {
        float* esm = (float*)(sm + SM_WT);        // [24][40]
        float* ssm = esm + 24 * 40;               // [24][128]
        int u = blockIdx.x;
        if (u < 90) {
            int l = u / 30, g0 = (u % 30) * 24;
            float t0 = g0 * 0.025f;
            int kmin = (int)ceilf((t0 - 1.6f) * 10.0f);            if (kmin < 0) kmin = 0;
            int kmax = (int)floorf((t0 + 0.575f + 1.6f) * 10.0f);  if (kmax > NKER - 1) kmax = NKER - 1;
            int nk = kmax - kmin + 1;                              // <= 39
            if (tid < 24 * 40) {
                int rr = tid / 40, kk = tid % 40;
                float e = 0.0f;
                if (kk < nk) {
                    float uu = (g0 + rr) * 0.025f - 0.1f * (float)(kmin + kk);
                    e = __expf(-10.0f * uu * uu);
                }
                esm[rr * 40 + kk] = e;
            }
            __syncthreads();
            {
                int f = tid & 127, rh = tid >> 7;          // 3 rows each (rh 0..7)
                const float* W1 = cf_W1 + l * NKER * FDIM;
                float b1f = cf_b1[l * FDIM + f];
#pragma unroll
                for (int q = 0; q < 3; q++) {
                    int rr = rh * 3 + q;
                    float acc = 0.0f;
                    for (int kk = 0; kk < nk; kk++)
                        acc = fmaf(esm[rr * 40 + kk], W1[(kmin + kk) * FDIM + f], acc);
                    ssm[rr * FDIM + f] = sspf(acc + b1f);
                }
            }
            __syncthreads();
            {
                int f = tid & 127, rh = tid >> 7;          // 3 rows each
                const float* W2 = cf_W2 + l * FDIM * FDIM;
                float b2f = cf_b2[l * FDIM + f];
                float a0 = b2f, a1 = b2f, a2 = b2f;
#pragma unroll 4
                for (int k = 0; k < FDIM; k++) {
                    float w = W2[k * FDIM + f];
                    a0 = fmaf(ssm[(rh * 3 + 0) * FDIM + k], w, a0);
                    a1 = fmaf(ssm[(rh * 3 + 1) * FDIM + k], w, a1);
                    a2 = fmaf(ssm[(rh * 3 + 2) * FDIM + k], w, a2);
                }
                int g = g0 + rh * 3;
                if (g < NG2)     g_WTABh[(l * NG2 + g) * FDIM + f]     = __float2half_rn(sspf(a0));
                if (g + 1 < NG2) g_WTABh[(l * NG2 + g + 1) * FDIM + f] = __float2half_rn(sspf(a1));
                if (g + 2 < NG2) g_WTABh[(l * NG2 + g + 2) * FDIM + f] = __float2half_rn(sspf(a2));
            }
        }
    }
    gbar(gen0 + (++nbar));   // o buf0 + WTAB published

    // ==================== layer loop ====================
    for (int l = 0; l < NLAYER; l++) {
        const float* oBuf = g_O[l & 1];
        // ---- conv: cps[a,f] = sum_j o[j,f] * lin_interp(WTAB_l, d_aj)[f] ----
        {
            // stage fp16 table slice (11 x uint4 per thread)
            uint4* dst = (uint4*)(sm + SM_WT);
            const uint4* src = (const uint4*)(g_WTABh + l * NG2 * FDIM);
#pragma unroll
            for (int it = 0; it < (NG2 * FDIM * 2 / 16) / NTH; it++)
                dst[tid + it * NTH] = src[tid + it * NTH];
            __syncthreads();

            const int fp = tid & 31;      // 4 features: fp*4 .. fp*4+3
            const int jg = tid >> 5;      // warp id 0..31, one j per warp
            const char*  Tbase = (const char*)(sm + SM_WT) + fp * 8;
            const char*  cwb = sm + SM_CWOFF;
            const __half2 ONE2 = __float2half2_rn(1.0f);

            float acc[4][4];
#pragma unroll
            for (int a = 0; a < 4; a++)
#pragma unroll
                for (int c = 0; c < 4; c++) acc[a][c] = 0.0f;

            const float* oPtr = oBuf + fp * 4;
            // o prefetch pipeline, depth 2 (L2-latency ~260cyc > 1 iter)
            float4 ovA = *(const float4*)(oPtr + jg * FDIM);
            float4 ovB = *(const float4*)(oPtr + (jg + 32) * FDIM);
            int j = jg;
#pragma unroll 2
            for (int it = 0; it < 16; it++, j += 32) {
                float4 ovC = ovA;
                if (it < 14) ovC = *(const float4*)(oPtr + (j + 64) * FDIM);
                const uint4* cwj = (const uint4*)(cwb + j * 32);   // broadcast
                uint4 A = cwj[0], B = cwj[1];
                unsigned offv[4] = {A.x, A.z, B.x, B.z};
                unsigned xhv[4]  = {A.y, A.w, B.y, B.w};
#pragma unroll
                for (int a = 0; a < 4; a++) {
                    __half2 xh  = *(__half2*)&xhv[a];
                    __half2 oxh = __hsub2(ONE2, xh);
                    const char* T = Tbase + offv[a];
                    uint2 q0 = *(const uint2*)(T);
                    uint2 q1 = *(const uint2*)(T + 256);
                    __half2 w0 = __hfma2(xh, *(__half2*)&q1.x,
                                 __hmul2(oxh, *(__half2*)&q0.x));
                    __half2 w1 = __hfma2(xh, *(__half2*)&q1.y,
                                 __hmul2(oxh, *(__half2*)&q0.y));
                    float2 wf0 = __half22float2(w0);
                    float2 wf1 = __half22float2(w1);
                    acc[a][0] = fmaf(ovA.x, wf0.x, acc[a][0]);
                    acc[a][1] = fmaf(ovA.y, wf0.y, acc[a][1]);
                    acc[a][2] = fmaf(ovA.z, wf1.x, acc[a][2]);
                    acc[a][3] = fmaf(ovA.w, wf1.y, acc[a][3]);
                }
                ovA = ovB; ovB = ovC;
            }

            // one partial per warp -> smem (aliases table region), split reduce
            __syncthreads();                      // all table reads done before overwrite
            float* red = (float*)(sm + SM_RED);   // [32][4][128]
#pragma unroll
            for (int a = 0; a < 4; a++)
                *(float4*)(red + (jg * 4 + a) * FDIM + fp * 4) =
                    make_float4(acc[a][0], acc[a][1], acc[a][2], acc[a][3]);
            __syncthreads();
            {
                int f = tid & 127, a = (tid >> 7) & 3, h = tid >> 9;
                float s = 0.0f;
#pragma unroll
                for (int g = 0; g < 16; g++)
                    s += red[((h * 16 + g) * 4 + a) * FDIM + f];
                p2[h * 512 + (tid & 511)] = s;
            }
            __syncthreads();
            if (tid < 512) cps[tid] = p2[tid] + p2[512 + tid];
            __syncthreads();
        }

        if (l < NLAYER - 1) {
            norm_phase(n_W1 + l * FDIM * FDIM, n_b1 + l * FDIM,
                       n_W2 + l * FDIM * FDIM, n_b2 + l * FDIM,
                       cps, hsm, (float*)(sm + SM_RED), p2, tid);
            atomwise_phase(aw_W + (l + 1) * FDIM * FDIM, aw_b + (l + 1) * FDIM,
                           hsm, g_O[(l + 1) & 1], p2, i0, tid);
            gbar(gen0 + (++nbar));   // new o published
        }
    }

    // ---- final norm + output head (CTA-local) ----
    norm_phase(n_W1 + 2 * FDIM * FDIM, n_b1 + 2 * FDIM,
               n_W2 + 2 * FDIM * FDIM, n_b2 + 2 * FDIM,
               cps, hsm, (float*)(sm + SM_RED), p2, tid);
    if (tid < 128) {
        int wid = tid >> 5, lane = tid & 31;
        const float* hrow = hsm + wid * FDIM;
        float acc = out_b1[lane];
#pragma unroll 8
        for (int k = 0; k < FDIM; k++)
            acc = fmaf(hrow[k], out_W1[k * 32 + lane], acc);
        float u = sspf(acc) * out_W2[lane];
#pragma unroll
        for (int off = 16; off > 0; off >>= 1)
            u += __shfl_down_sync(0xffffffffu, u, off);
        if (lane == 0) out[i0 + wid] = u + out_b2[0];
    }
}

// ---------------------------------------------------------------------------
extern "C" void kernel_launch(void* const* d_in, const int* in_sizes, int n_in,
                              void* d_out, int out_size) {
    const int*   x      = (const int*)d_in[0];
    const float* r      = (const float*)d_in[1];
    const float* emb    = (const float*)d_in[2];
    const float* aw_W   = (const float*)d_in[3];
    const float* aw_b   = (const float*)d_in[4];
    const float* cf_W1  = (const float*)d_in[5];
    const float* cf_b1  = (const float*)d_in[6];
    const float* cf_W2  = (const float*)d_in[7];
    const float* cf_b2  = (const float*)d_in[8];
    const float* n_W1   = (const float*)d_in[9];
    const float* n_b1   = (const float*)d_in[10];
    const float* n_W2   = (const float*)d_in[11];
    const float* n_b2   = (const float*)d_in[12];
    const float* out_W1 = (const float*)d_in[13];
    const float* out_b1 = (const float*)d_in[14];
    const float* out_W2 = (const float*)d_in[15];
    const float* out_b2 = (const float*)d_in[16];
    float* out = (float*)d_out;

    cudaFuncSetAttribute(schnet_fused, cudaFuncAttributeMaxDynamicSharedMemorySize,
                         SM_TOTAL);
    schnet_fused<<<GRID, NTH, SM_TOTAL>>>(
        x, r, emb, aw_W, aw_b, cf_W1, cf_b1, cf_W2, cf_b2,
        n_W1, n_b1, n_W2, n_b2, out_W1, out_b1, out_W2, out_b2, out);
}